// round 14
// baseline (speedup 1.0000x reference)
#include <cuda_runtime.h>
#include <cuda_fp16.h>
#include <math.h>

#define BATCH 16384
#define NCO   64
#define NFI   128
#define NSF   192
#define HID   64

// ---------------- scratch (device global; no allocation allowed) ----------------
__device__ float g_z[BATCH * NSF];

__device__ __forceinline__ float sigmoidf_(float z) { return 1.0f / (1.0f + __expf(-z)); }

__device__ __forceinline__ void split_h(float v, unsigned short& hi, unsigned short& lo) {
    const __half h = __float2half_rn(v);
    hi = __half_as_ushort(h);
    lo = __half_as_ushort(__float2half_rn(v - __half2float(h)));
}
__device__ __forceinline__ unsigned pack2(unsigned short l, unsigned short h) {
    return (unsigned)l | ((unsigned)h << 16);
}

__device__ __forceinline__ void mma_f16(float& c0, float& c1, float& c2, float& c3,
    unsigned a0, unsigned a1, unsigned a2, unsigned a3, unsigned b0, unsigned b1) {
    asm("mma.sync.aligned.m16n8k16.row.col.f32.f16.f16.f32 "
        "{%0,%1,%2,%3},{%4,%5,%6,%7},{%8,%9},{%0,%1,%2,%3};"
        : "+f"(c0), "+f"(c1), "+f"(c2), "+f"(c3)
        : "r"(a0), "r"(a1), "r"(a2), "r"(a3), "r"(b0), "r"(b1));
}

__device__ __forceinline__ float wred(float v) {
#pragma unroll
    for (int o = 16; o; o >>= 1) v += __shfl_xor_sync(0xffffffffu, v, o);
    return v;
}
__device__ __forceinline__ float wscan_incl(float v) {
    const int lane = threadIdx.x & 31;
    float x = v;
#pragma unroll
    for (int o = 1; o < 32; o <<= 1) {
        float n = __shfl_up_sync(0xffffffffu, x, o);
        if (lane >= o) x += n;
    }
    return x;
}

// ---------------- fused MLP (R7 mma path) + per-ray postprocess ----------------
// COARSE: TPW=8  -> warp covers 2 complete rays; lanes 0/16 each replay the R11
//                  scalar coarse_post chain (render + cdf + inverse-CDF + merge)
//                  bit-exactly, hidden under other warps' tensor work.
// FINE:   TPW=12 -> warp covers 1 complete ray; all 32 lanes run the R11-validated
//                  warp fine_render on shared rgb/sig.
template <int NS, bool COARSE, int TPW>
__global__ void __launch_bounds__(128) mlp_fused_kernel(
    const float* __restrict__ org,  const float* __restrict__ dirv,
    const float* __restrict__ nearp,const float* __restrict__ farp,
    const float* __restrict__ w1,   const float* __restrict__ b1,
    const float* __restrict__ w2,   const float* __restrict__ b2,
    const float* __restrict__ wr,   const float* __restrict__ br,
    const float* __restrict__ wd,   const float* __restrict__ bd,
    const float* __restrict__ bkgd, float* __restrict__ out)
{
    __shared__ __align__(16) uint4 sFragB[32 * 32];      // 16 KB
    __shared__ __align__(16) float sL1[HID * 4];
    __shared__ __align__(16) float sHD[HID * 4];
    __shared__ float sB2[HID];
    __shared__ float sBh[4];
    __shared__ float ssig[4][TPW * 16];
    __shared__ float srgb[4][TPW * 48];

    const int tid = threadIdx.x;
    for (int e = tid; e < 32 * 32; e += 128) {
        const int pair = e >> 5, lv = e & 31;
        const int nc = pair >> 2, kc = pair & 3;
        const int gv = lv >> 2, tv = lv & 3;
        const int n  = nc * 8 + gv;
        const int k0 = 16 * kc + 2 * tv;
        const int k2 = k0 + 8;
        unsigned short h00, l00, h01, l01, h20, l20, h21, l21;
        split_h(w2[(k0    ) * HID + n], h00, l00);
        split_h(w2[(k0 + 1) * HID + n], h01, l01);
        split_h(w2[(k2    ) * HID + n], h20, l20);
        split_h(w2[(k2 + 1) * HID + n], h21, l21);
        sFragB[e] = make_uint4(pack2(h00, h01), pack2(h20, h21),
                               pack2(l00, l01), pack2(l20, l21));
    }
    for (int i = tid; i < HID; i += 128) {
        sL1[4*i+0] = w1[i]; sL1[4*i+1] = w1[64+i]; sL1[4*i+2] = w1[128+i]; sL1[4*i+3] = b1[i];
        sHD[4*i+0] = wr[3*i]; sHD[4*i+1] = wr[3*i+1]; sHD[4*i+2] = wr[3*i+2]; sHD[4*i+3] = wd[i];
        sB2[i] = b2[i];
    }
    if (tid == 0) { sBh[0] = br[0]; sBh[1] = br[1]; sBh[2] = br[2]; sBh[3] = bd[0]; }
    __syncthreads();

    const int lane = tid & 31;
    const int gid  = lane >> 2;
    const int tig  = lane & 3;
    const int wIdx = tid >> 5;
    const int warpGlobal = blockIdx.x * 4 + wIdx;

    // ================= MLP phase (R7 math, outputs to shared) =================
#pragma unroll 1
    for (int it = 0; it < TPW; ++it) {
        const int tileIdx = warpGlobal * TPW + it;
        const int s0 = tileIdx * 16;
        const int b  = s0 / NS;

        const float ox = org[3*b], oy = org[3*b+1], oz = org[3*b+2];
        const float dx = dirv[3*b], dy = dirv[3*b+1], dz = dirv[3*b+2];
        float t0, t1;
        if (COARSE) {
            const float nb = nearp[b], fb = farp[b];
            const int i0 = (s0 % NS) + gid, i1 = i0 + 8;
            float q0 = (i0 == 63) ? 1.0f : (float)i0 * (1.0f / 63.0f);
            float q1 = (i1 == 63) ? 1.0f : (float)i1 * (1.0f / 63.0f);
            t0 = nb * (1.0f - q0) + fb * q0;
            t1 = nb * (1.0f - q1) + fb * q1;
        } else {
            t0 = g_z[s0 + gid];
            t1 = g_z[s0 + gid + 8];
        }
        const float x00 = fmaf(t0, dx, ox), x01 = fmaf(t0, dy, oy), x02 = fmaf(t0, dz, oz);
        const float x10 = fmaf(t1, dx, ox), x11 = fmaf(t1, dy, oy), x12 = fmaf(t1, dz, oz);

        unsigned Ah[4][4], Al[4][4];
#pragma unroll
        for (int kc = 0; kc < 4; kc++) {
            unsigned short hg[4], lg[4], hG[4], lG[4];
#pragma unroll
            for (int q = 0; q < 4; q++) {
                const int c = 16 * kc + ((q >> 1) << 3) + 2 * tig + (q & 1);
                const float4 L = *(const float4*)&sL1[4 * c];
                const float hA = fmaxf(fmaf(x02, L.z, fmaf(x01, L.y, fmaf(x00, L.x, L.w))), 0.0f);
                const float hB = fmaxf(fmaf(x12, L.z, fmaf(x11, L.y, fmaf(x10, L.x, L.w))), 0.0f);
                split_h(hA, hg[q], lg[q]);
                split_h(hB, hG[q], lG[q]);
            }
            Ah[kc][0] = pack2(hg[0], hg[1]); Ah[kc][1] = pack2(hG[0], hG[1]);
            Ah[kc][2] = pack2(hg[2], hg[3]); Ah[kc][3] = pack2(hG[2], hG[3]);
            Al[kc][0] = pack2(lg[0], lg[1]); Al[kc][1] = pack2(lG[0], lG[1]);
            Al[kc][2] = pack2(lg[2], lg[3]); Al[kc][3] = pack2(lG[2], lG[3]);
        }

        float hp0[4] = {0.f, 0.f, 0.f, 0.f};
        float hp1[4] = {0.f, 0.f, 0.f, 0.f};
#pragma unroll 1
        for (int nc = 0; nc < 8; nc++) {
            const int j0 = nc * 8 + 2 * tig;
            float c0 = sB2[j0], c1 = sB2[j0 + 1];
            float c2 = c0, c3 = c1;
            const uint4* frag = &sFragB[(nc * 4) * 32 + lane];
#pragma unroll
            for (int kc = 0; kc < 4; kc++) {
                const uint4 f = frag[kc * 32];
                mma_f16(c0, c1, c2, c3,
                        Ah[kc][0], Ah[kc][1], Ah[kc][2], Ah[kc][3], f.x, f.y);
                mma_f16(c0, c1, c2, c3,
                        Al[kc][0], Al[kc][1], Al[kc][2], Al[kc][3], f.x, f.y);
                mma_f16(c0, c1, c2, c3,
                        Ah[kc][0], Ah[kc][1], Ah[kc][2], Ah[kc][3], f.z, f.w);
            }
            const float4 H0 = *(const float4*)&sHD[4 * j0];
            const float4 H1 = *(const float4*)&sHD[4 * (j0 + 1)];
            const float v00 = fmaxf(c0, 0.f), v01 = fmaxf(c1, 0.f);
            const float v10 = fmaxf(c2, 0.f), v11 = fmaxf(c3, 0.f);
            hp0[0] = fmaf(v00, H0.x, fmaf(v01, H1.x, hp0[0]));
            hp0[1] = fmaf(v00, H0.y, fmaf(v01, H1.y, hp0[1]));
            hp0[2] = fmaf(v00, H0.z, fmaf(v01, H1.z, hp0[2]));
            hp0[3] = fmaf(v00, H0.w, fmaf(v01, H1.w, hp0[3]));
            hp1[0] = fmaf(v10, H0.x, fmaf(v11, H1.x, hp1[0]));
            hp1[1] = fmaf(v10, H0.y, fmaf(v11, H1.y, hp1[1]));
            hp1[2] = fmaf(v10, H0.z, fmaf(v11, H1.z, hp1[2]));
            hp1[3] = fmaf(v10, H0.w, fmaf(v11, H1.w, hp1[3]));
        }

#pragma unroll
        for (int c = 0; c < 4; c++) {
            hp0[c] += __shfl_xor_sync(0xffffffffu, hp0[c], 1);
            hp0[c] += __shfl_xor_sync(0xffffffffu, hp0[c], 2);
            hp1[c] += __shfl_xor_sync(0xffffffffu, hp1[c], 1);
            hp1[c] += __shfl_xor_sync(0xffffffffu, hp1[c], 2);
        }
        if (tig == 0) {
            const int la = it * 16 + gid;
            const int lb = la + 8;
            srgb[wIdx][3*la+0] = sigmoidf_(hp0[0] + sBh[0]);
            srgb[wIdx][3*la+1] = sigmoidf_(hp0[1] + sBh[1]);
            srgb[wIdx][3*la+2] = sigmoidf_(hp0[2] + sBh[2]);
            ssig[wIdx][la] = fmaxf(hp0[3] + sBh[3], 0.f);
            srgb[wIdx][3*lb+0] = sigmoidf_(hp1[0] + sBh[0]);
            srgb[wIdx][3*lb+1] = sigmoidf_(hp1[1] + sBh[1]);
            srgb[wIdx][3*lb+2] = sigmoidf_(hp1[2] + sBh[2]);
            ssig[wIdx][lb] = fmaxf(hp1[3] + sBh[3], 0.f);
        }
    }
    __syncwarp();

    // ================= post phase =================
    if (COARSE) {
        // lanes 0 and 16 each run the R11 scalar coarse_post chain for one ray
        if ((lane & 15) == 0) {
            const int sub = lane >> 4;
            const int b = warpGlobal * 2 + sub;
            const float* sig = &ssig[wIdx][sub * 64];
            const float* rgbp = &srgb[wIdx][sub * 192];

            const float nb = nearp[b], fb = farp[b];
            const float n0 = nearp[0], f0 = farp[0];
            const float dxx = dirv[3*b+0], dyy = dirv[3*b+1], dzz = dirv[3*b+2];
            const float nrm = sqrtf(dxx*dxx + dyy*dyy + dzz*dzz);
            const float o0x = org[0],  o0y = org[1],  o0z = org[2];
            const float d0x = dirv[0], d0y = dirv[1], d0z = dirv[2];

            auto TV  = [&](int i) -> float {
                float tq = (i == 63) ? 1.0f : (float)i * (1.0f / 63.0f);
                return nb * (1.0f - tq) + fb * tq;
            };
            auto TV0 = [&](int i) -> float {
                float tq = (i == 63) ? 1.0f : (float)i * (1.0f / 63.0f);
                return n0 * (1.0f - tq) + f0 * tq;
            };

            float w[NCO];
            float S = 0.f, acc = 0.f, depth = 0.f, wt0 = 0.f, c0 = 0.f, c1 = 0.f, c2 = 0.f;
            float tcur = TV(0);
#pragma unroll 1
            for (int i = 0; i < NCO; i++) {
                const float tnext = (i < 63) ? TV(i + 1) : tcur;
                const float td    = (i < 63) ? (tnext - tcur) : 1e10f;
                const float dd    = sig[i] * td * nrm;
                const float T     = __expf(-S);
                const float alpha = 1.0f - __expf(-dd);
                const float wi    = alpha * T;
                S += dd;
                w[i] = wi;
                acc += wi;
                depth = fmaf(wi, tcur, depth);
                wt0   = fmaf(wi, TV0(i), wt0);
                c0 = fmaf(wi, rgbp[3*i+0], c0);
                c1 = fmaf(wi, rgbp[3*i+1], c1);
                c2 = fmaf(wi, rgbp[3*i+2], c2);
                tcur = tnext;
            }
            float* ob = out + (size_t)b * 16;
            ob[0] = c0 + bkgd[0] * (1.0f - acc);
            ob[1] = c1 + bkgd[1] * (1.0f - acc);
            ob[2] = c2 + bkgd[2] * (1.0f - acc);
            ob[3] = depth;
            ob[4] = acc;
            ob[5] = acc * o0x + wt0 * d0x;
            ob[6] = acc * o0y + wt0 * d0y;
            ob[7] = acc * o0z + wt0 * d0z;

            float ws = 0.f;
#pragma unroll 1
            for (int k = 1; k <= 62; k++) ws += w[k];
            const float pad = fmaxf(1e-5f - ws, 0.0f);
            const float add = pad * (1.0f / 62.0f);
            ws += pad;
            const float inv = 1.0f / ws;
            float cdf[64];
            cdf[0] = 0.0f;
            float cs = 0.f;
#pragma unroll 1
            for (int k = 1; k <= 61; k++) {
                cs += (w[k] + add) * inv;
                cdf[k] = fminf(cs, 1.0f);
            }
            cdf[62] = 1.0f;

            auto BIN = [&](int k) -> float { return 0.5f * (TV(k) + TV(k + 1)); };

            const float ueps = 1.1920929e-07f;
            const float du = (1.0f - ueps) * (1.0f / 127.0f);
            int idx = 0, ti = 0, p = 0;
            const size_t base = (size_t)b * NSF;
#pragma unroll 1
            for (int s = 0; s < NFI; s++) {
                const float u = (s == 127) ? (1.0f - ueps) : (float)s * du;
                while (idx < 61 && cdf[idx + 1] <= u) idx++;
                const float gg0 = cdf[idx], gg1 = cdf[idx + 1];
                float tt = (u - gg0) / (gg1 - gg0);
                if (!(tt == tt)) tt = 0.0f;
                tt = fminf(fmaxf(tt, 0.0f), 1.0f);
                const float bb0 = BIN(idx);
                const float z = fmaf(tt, BIN(idx + 1) - bb0, bb0);
                while (ti < NCO && TV(ti) <= z) { g_z[base + p] = TV(ti); p++; ti++; }
                g_z[base + p] = z; p++;
            }
            while (ti < NCO) { g_z[base + p] = TV(ti); p++; ti++; }
        }
    } else {
        // R11-validated warp fine_render; rgb/sig from shared
        const int b = warpGlobal;
        const float dxx = dirv[3*b+0], dyy = dirv[3*b+1], dzz = dirv[3*b+2];
        const float nrm = sqrtf(dxx*dxx + dyy*dyy + dzz*dzz);

        const float* zr = g_z + (size_t)b * NSF;
        const int i0 = 6 * lane;

        float z[7];
#pragma unroll
        for (int r = 0; r < 7; r++) {
            const int i = i0 + r;
            z[r] = (i < NSF) ? zr[i] : 0.0f;
        }
        float dd[6], pre[6];
        float tot = 0.f;   // scan excludes the last sample's ~1e10 dd (alpha-only term)
#pragma unroll
        for (int r = 0; r < 6; r++) {
            const int i = i0 + r;
            const float td = (i < NSF - 1) ? (z[r + 1] - z[r]) : 1e10f;
            dd[r] = ssig[wIdx][i] * td * nrm;
            pre[r] = tot;
            if (i < NSF - 1) tot += dd[r];
        }
        const float excl = wscan_incl(tot) - tot;

        float acc = 0.f, dep = 0.f, wz0 = 0.f, c0 = 0.f, c1 = 0.f, c2 = 0.f;
#pragma unroll
        for (int r = 0; r < 6; r++) {
            const int i = i0 + r;
            const float wi = (1.0f - __expf(-dd[r])) * __expf(-(excl + pre[r]));
            acc += wi;
            dep = fmaf(wi, z[r], dep);
            wz0 = fmaf(wi, g_z[i], wz0);      // samples_f[0] quirk: ray-0 z positions
            c0 = fmaf(wi, srgb[wIdx][3*i+0], c0);
            c1 = fmaf(wi, srgb[wIdx][3*i+1], c1);
            c2 = fmaf(wi, srgb[wIdx][3*i+2], c2);
        }
        acc = wred(acc); dep = wred(dep); wz0 = wred(wz0);
        c0 = wred(c0); c1 = wred(c1); c2 = wred(c2);
        if (lane == 0) {
            float* ob = out + (size_t)b * 16;
            ob[8]  = c0 + bkgd[0] * (1.0f - acc);
            ob[9]  = c1 + bkgd[1] * (1.0f - acc);
            ob[10] = c2 + bkgd[2] * (1.0f - acc);
            ob[11] = dep;
            ob[12] = acc;
            ob[13] = acc * org[0]  + wz0 * dirv[0];
            ob[14] = acc * org[1]  + wz0 * dirv[1];
            ob[15] = acc * org[2]  + wz0 * dirv[2];
        }
    }
}

// ---------------- launch ----------------
extern "C" void kernel_launch(void* const* d_in, const int* in_sizes, int n_in,
                              void* d_out, int out_size)
{
    const float* org   = (const float*)d_in[0];
    const float* dirv  = (const float*)d_in[1];
    const float* nearp = (const float*)d_in[2];
    const float* farp  = (const float*)d_in[3];
    const float* bkgd  = (const float*)d_in[4];

    const float* w1c = (const float*)d_in[5];
    const float* b1c = (const float*)d_in[6];
    const float* w2c = (const float*)d_in[7];
    const float* b2c = (const float*)d_in[8];
    const float* wrc = (const float*)d_in[9];
    const float* brc = (const float*)d_in[10];
    const float* wdc = (const float*)d_in[11];
    const float* bdc = (const float*)d_in[12];

    const float* w1f = (const float*)d_in[13];
    const float* b1f = (const float*)d_in[14];
    const float* w2f = (const float*)d_in[15];
    const float* b2f = (const float*)d_in[16];
    const float* wrf = (const float*)d_in[17];
    const float* brf = (const float*)d_in[18];
    const float* wdf = (const float*)d_in[19];
    const float* bdf = (const float*)d_in[20];

    float* out = (float*)d_out;

    // K1: coarse MLP + fused scalar coarse_post.
    //     65536 tiles / (TPW=8) = 8192 warps -> 2048 blocks; warp = 2 rays.
    mlp_fused_kernel<NCO, true, 8><<<2048, 128>>>(
        org, dirv, nearp, farp, w1c, b1c, w2c, b2c, wrc, brc, wdc, bdc, bkgd, out);

    // K2: fine MLP + fused warp fine_render.
    //     196608 tiles / (TPW=12) = 16384 warps -> 4096 blocks; warp = 1 ray.
    mlp_fused_kernel<NSF, false, 12><<<4096, 128>>>(
        org, dirv, nearp, farp, w1f, b1f, w2f, b2f, wrf, brf, wdf, bdf, bkgd, out);
}

// round 15
// speedup vs baseline: 1.6388x; 1.6388x over previous
#include <cuda_runtime.h>
#include <cuda_fp16.h>
#include <math.h>

#define BATCH 16384
#define NCO   64
#define NFI   128
#define NSF   192
#define HID   64

// ---------------- scratch (device globals; no allocation allowed) ----------------
__device__ float g_rgb_c[BATCH * NCO * 3];
__device__ float g_sig_c[BATCH * NCO];
__device__ float g_z    [BATCH * NSF];
__device__ float g_rgb_f[BATCH * NSF * 3];
__device__ float g_sig_f[BATCH * NSF];

__device__ __forceinline__ float sigmoidf_(float z) { return 1.0f / (1.0f + __expf(-z)); }

// split fp32 into fp16 hi + fp16 lo (hi+lo carries ~22 mantissa bits)
__device__ __forceinline__ void split_h(float v, unsigned short& hi, unsigned short& lo) {
    const __half h = __float2half_rn(v);
    hi = __half_as_ushort(h);
    lo = __half_as_ushort(__float2half_rn(v - __half2float(h)));
}
__device__ __forceinline__ unsigned pack2(unsigned short l, unsigned short h) {
    return (unsigned)l | ((unsigned)h << 16);
}

__device__ __forceinline__ void mma_f16(float& c0, float& c1, float& c2, float& c3,
    unsigned a0, unsigned a1, unsigned a2, unsigned a3, unsigned b0, unsigned b1) {
    asm("mma.sync.aligned.m16n8k16.row.col.f32.f16.f16.f32 "
        "{%0,%1,%2,%3},{%4,%5,%6,%7},{%8,%9},{%0,%1,%2,%3};"
        : "+f"(c0), "+f"(c1), "+f"(c2), "+f"(c3)
        : "r"(a0), "r"(a1), "r"(a2), "r"(a3), "r"(b0), "r"(b1));
}

// warp helpers
__device__ __forceinline__ float wred(float v) {
#pragma unroll
    for (int o = 16; o; o >>= 1) v += __shfl_xor_sync(0xffffffffu, v, o);
    return v;
}
__device__ __forceinline__ float wscan_incl(float v) {
    const int lane = threadIdx.x & 31;
    float x = v;
#pragma unroll
    for (int o = 1; o < 32; o <<= 1) {
        float n = __shfl_up_sync(0xffffffffu, x, o);
        if (lane >= o) x += n;
    }
    return x;
}

// ---------------- MLP via mma.sync f16 (3-term split), warp per 16-sample tile ----------------
// nc-chunks processed in PAIRS with independent accumulators: interleaved mma chains
// double ILP on the HMMA dependency path (R14 ncu: issue 46%, tensor 34% -> latency-bound).
// Per-output accumulation order unchanged -> bit-identical to R7/R11 results.
template <int NS, bool COARSE, int TPW>
__global__ void __launch_bounds__(128) mlp_mma_kernel(
    const float* __restrict__ org,  const float* __restrict__ dirv,
    const float* __restrict__ nearp,const float* __restrict__ farp,
    const float* __restrict__ w1,   const float* __restrict__ b1,
    const float* __restrict__ w2,   const float* __restrict__ b2,
    const float* __restrict__ wr,   const float* __restrict__ br,
    const float* __restrict__ wd,   const float* __restrict__ bd)
{
    __shared__ __align__(16) uint4 sFragB[32 * 32];      // 16 KB
    __shared__ __align__(16) float sL1[HID * 4];
    __shared__ __align__(16) float sHD[HID * 4];
    __shared__ float sB2[HID];
    __shared__ float sBh[4];

    const int tid = threadIdx.x;
    for (int e = tid; e < 32 * 32; e += 128) {
        const int pair = e >> 5, lv = e & 31;
        const int nc = pair >> 2, kc = pair & 3;
        const int gv = lv >> 2, tv = lv & 3;
        const int n  = nc * 8 + gv;
        const int k0 = 16 * kc + 2 * tv;
        const int k2 = k0 + 8;
        unsigned short h00, l00, h01, l01, h20, l20, h21, l21;
        split_h(w2[(k0    ) * HID + n], h00, l00);
        split_h(w2[(k0 + 1) * HID + n], h01, l01);
        split_h(w2[(k2    ) * HID + n], h20, l20);
        split_h(w2[(k2 + 1) * HID + n], h21, l21);
        sFragB[e] = make_uint4(pack2(h00, h01), pack2(h20, h21),
                               pack2(l00, l01), pack2(l20, l21));
    }
    for (int i = tid; i < HID; i += 128) {
        sL1[4*i+0] = w1[i]; sL1[4*i+1] = w1[64+i]; sL1[4*i+2] = w1[128+i]; sL1[4*i+3] = b1[i];
        sHD[4*i+0] = wr[3*i]; sHD[4*i+1] = wr[3*i+1]; sHD[4*i+2] = wr[3*i+2]; sHD[4*i+3] = wd[i];
        sB2[i] = b2[i];
    }
    if (tid == 0) { sBh[0] = br[0]; sBh[1] = br[1]; sBh[2] = br[2]; sBh[3] = bd[0]; }
    __syncthreads();

    const int lane = tid & 31;
    const int gid  = lane >> 2;
    const int tig  = lane & 3;
    const int warpGlobal = blockIdx.x * 4 + (tid >> 5);

#pragma unroll 1
    for (int it = 0; it < TPW; ++it) {
        const int tileIdx = warpGlobal * TPW + it;
        const int s0 = tileIdx * 16;
        const int b  = s0 / NS;

        const float ox = org[3*b], oy = org[3*b+1], oz = org[3*b+2];
        const float dx = dirv[3*b], dy = dirv[3*b+1], dz = dirv[3*b+2];
        float t0, t1;
        if (COARSE) {
            const float nb = nearp[b], fb = farp[b];
            const int i0 = (s0 % NS) + gid, i1 = i0 + 8;
            float q0 = (i0 == 63) ? 1.0f : (float)i0 * (1.0f / 63.0f);
            float q1 = (i1 == 63) ? 1.0f : (float)i1 * (1.0f / 63.0f);
            t0 = nb * (1.0f - q0) + fb * q0;
            t1 = nb * (1.0f - q1) + fb * q1;
        } else {
            t0 = g_z[s0 + gid];
            t1 = g_z[s0 + gid + 8];
        }
        const float x00 = fmaf(t0, dx, ox), x01 = fmaf(t0, dy, oy), x02 = fmaf(t0, dz, oz);
        const float x10 = fmaf(t1, dx, ox), x11 = fmaf(t1, dy, oy), x12 = fmaf(t1, dz, oz);

        unsigned Ah[4][4], Al[4][4];
#pragma unroll
        for (int kc = 0; kc < 4; kc++) {
            unsigned short hg[4], lg[4], hG[4], lG[4];
#pragma unroll
            for (int q = 0; q < 4; q++) {
                const int c = 16 * kc + ((q >> 1) << 3) + 2 * tig + (q & 1);
                const float4 L = *(const float4*)&sL1[4 * c];
                const float hA = fmaxf(fmaf(x02, L.z, fmaf(x01, L.y, fmaf(x00, L.x, L.w))), 0.0f);
                const float hB = fmaxf(fmaf(x12, L.z, fmaf(x11, L.y, fmaf(x10, L.x, L.w))), 0.0f);
                split_h(hA, hg[q], lg[q]);
                split_h(hB, hG[q], lG[q]);
            }
            Ah[kc][0] = pack2(hg[0], hg[1]); Ah[kc][1] = pack2(hG[0], hG[1]);
            Ah[kc][2] = pack2(hg[2], hg[3]); Ah[kc][3] = pack2(hG[2], hG[3]);
            Al[kc][0] = pack2(lg[0], lg[1]); Al[kc][1] = pack2(lG[0], lG[1]);
            Al[kc][2] = pack2(lg[2], lg[3]); Al[kc][3] = pack2(lG[2], lG[3]);
        }

        float hp0[4] = {0.f, 0.f, 0.f, 0.f};
        float hp1[4] = {0.f, 0.f, 0.f, 0.f};
#pragma unroll 1
        for (int nc = 0; nc < 8; nc += 2) {
            const int j0 = nc * 8 + 2 * tig;
            const int j1 = (nc + 1) * 8 + 2 * tig;
            float a0 = sB2[j0], a1 = sB2[j0 + 1];
            float a2 = a0, a3 = a1;
            float e0 = sB2[j1], e1 = sB2[j1 + 1];
            float e2 = e0, e3 = e1;
            const uint4* fragA = &sFragB[(nc * 4) * 32 + lane];
            const uint4* fragE = &sFragB[((nc + 1) * 4) * 32 + lane];
#pragma unroll
            for (int kc = 0; kc < 4; kc++) {
                const uint4 fA = fragA[kc * 32];
                const uint4 fE = fragE[kc * 32];
                mma_f16(a0, a1, a2, a3,
                        Ah[kc][0], Ah[kc][1], Ah[kc][2], Ah[kc][3], fA.x, fA.y);
                mma_f16(e0, e1, e2, e3,
                        Ah[kc][0], Ah[kc][1], Ah[kc][2], Ah[kc][3], fE.x, fE.y);
                mma_f16(a0, a1, a2, a3,
                        Al[kc][0], Al[kc][1], Al[kc][2], Al[kc][3], fA.x, fA.y);
                mma_f16(e0, e1, e2, e3,
                        Al[kc][0], Al[kc][1], Al[kc][2], Al[kc][3], fE.x, fE.y);
                mma_f16(a0, a1, a2, a3,
                        Ah[kc][0], Ah[kc][1], Ah[kc][2], Ah[kc][3], fA.z, fA.w);
                mma_f16(e0, e1, e2, e3,
                        Ah[kc][0], Ah[kc][1], Ah[kc][2], Ah[kc][3], fE.z, fE.w);
            }
            // heads for chunk nc
            {
                const float4 H0 = *(const float4*)&sHD[4 * j0];
                const float4 H1 = *(const float4*)&sHD[4 * (j0 + 1)];
                const float v00 = fmaxf(a0, 0.f), v01 = fmaxf(a1, 0.f);
                const float v10 = fmaxf(a2, 0.f), v11 = fmaxf(a3, 0.f);
                hp0[0] = fmaf(v00, H0.x, fmaf(v01, H1.x, hp0[0]));
                hp0[1] = fmaf(v00, H0.y, fmaf(v01, H1.y, hp0[1]));
                hp0[2] = fmaf(v00, H0.z, fmaf(v01, H1.z, hp0[2]));
                hp0[3] = fmaf(v00, H0.w, fmaf(v01, H1.w, hp0[3]));
                hp1[0] = fmaf(v10, H0.x, fmaf(v11, H1.x, hp1[0]));
                hp1[1] = fmaf(v10, H0.y, fmaf(v11, H1.y, hp1[1]));
                hp1[2] = fmaf(v10, H0.z, fmaf(v11, H1.z, hp1[2]));
                hp1[3] = fmaf(v10, H0.w, fmaf(v11, H1.w, hp1[3]));
            }
            // heads for chunk nc+1
            {
                const float4 H0 = *(const float4*)&sHD[4 * j1];
                const float4 H1 = *(const float4*)&sHD[4 * (j1 + 1)];
                const float v00 = fmaxf(e0, 0.f), v01 = fmaxf(e1, 0.f);
                const float v10 = fmaxf(e2, 0.f), v11 = fmaxf(e3, 0.f);
                hp0[0] = fmaf(v00, H0.x, fmaf(v01, H1.x, hp0[0]));
                hp0[1] = fmaf(v00, H0.y, fmaf(v01, H1.y, hp0[1]));
                hp0[2] = fmaf(v00, H0.z, fmaf(v01, H1.z, hp0[2]));
                hp0[3] = fmaf(v00, H0.w, fmaf(v01, H1.w, hp0[3]));
                hp1[0] = fmaf(v10, H0.x, fmaf(v11, H1.x, hp1[0]));
                hp1[1] = fmaf(v10, H0.y, fmaf(v11, H1.y, hp1[1]));
                hp1[2] = fmaf(v10, H0.z, fmaf(v11, H1.z, hp1[2]));
                hp1[3] = fmaf(v10, H0.w, fmaf(v11, H1.w, hp1[3]));
            }
        }

#pragma unroll
        for (int c = 0; c < 4; c++) {
            hp0[c] += __shfl_xor_sync(0xffffffffu, hp0[c], 1);
            hp0[c] += __shfl_xor_sync(0xffffffffu, hp0[c], 2);
            hp1[c] += __shfl_xor_sync(0xffffffffu, hp1[c], 1);
            hp1[c] += __shfl_xor_sync(0xffffffffu, hp1[c], 2);
        }
        if (tig == 0) {
            float* rgb = COARSE ? g_rgb_c : g_rgb_f;
            float* sg  = COARSE ? g_sig_c : g_sig_f;
            const int sA = s0 + gid, sB = s0 + gid + 8;
            rgb[3*sA+0] = sigmoidf_(hp0[0] + sBh[0]);
            rgb[3*sA+1] = sigmoidf_(hp0[1] + sBh[1]);
            rgb[3*sA+2] = sigmoidf_(hp0[2] + sBh[2]);
            sg[sA] = fmaxf(hp0[3] + sBh[3], 0.f);
            rgb[3*sB+0] = sigmoidf_(hp1[0] + sBh[0]);
            rgb[3*sB+1] = sigmoidf_(hp1[1] + sBh[1]);
            rgb[3*sB+2] = sigmoidf_(hp1[2] + sBh[2]);
            sg[sB] = fmaxf(hp1[3] + sBh[3], 0.f);
        }
    }
}

// ---------------- coarse render + inverse-CDF sampling + sorted merge (R11 scalar, verbatim) ----------------
__global__ void coarse_post_kernel(
    const float* __restrict__ org, const float* __restrict__ dirv,
    const float* __restrict__ nearp, const float* __restrict__ farp,
    const float* __restrict__ bkgd, float* __restrict__ out)
{
    const int b = blockIdx.x * blockDim.x + threadIdx.x;
    if (b >= BATCH) return;

    const float nb = nearp[b], fb = farp[b];
    const float n0 = nearp[0], f0 = farp[0];
    const float dxx = dirv[3*b+0], dyy = dirv[3*b+1], dzz = dirv[3*b+2];
    const float nrm = sqrtf(dxx*dxx + dyy*dyy + dzz*dzz);
    const float o0x = org[0],  o0y = org[1],  o0z = org[2];
    const float d0x = dirv[0], d0y = dirv[1], d0z = dirv[2];

    auto TV  = [&](int i) -> float {
        float tq = (i == 63) ? 1.0f : (float)i * (1.0f / 63.0f);
        return nb * (1.0f - tq) + fb * tq;
    };
    auto TV0 = [&](int i) -> float {
        float tq = (i == 63) ? 1.0f : (float)i * (1.0f / 63.0f);
        return n0 * (1.0f - tq) + f0 * tq;
    };

    float w[NCO];
    float S = 0.f, acc = 0.f, depth = 0.f, wt0 = 0.f, c0 = 0.f, c1 = 0.f, c2 = 0.f;
    float tcur = TV(0);
    for (int i = 0; i < NCO; i++) {
        const float tnext = (i < 63) ? TV(i + 1) : tcur;
        const float td    = (i < 63) ? (tnext - tcur) : 1e10f;
        const float dd    = g_sig_c[b * NCO + i] * td * nrm;
        const float T     = __expf(-S);
        const float alpha = 1.0f - __expf(-dd);
        const float wi    = alpha * T;
        S += dd;
        w[i] = wi;
        acc += wi;
        depth = fmaf(wi, tcur, depth);
        wt0   = fmaf(wi, TV0(i), wt0);
        const float* rp = &g_rgb_c[(size_t)(b * NCO + i) * 3];
        c0 = fmaf(wi, rp[0], c0);
        c1 = fmaf(wi, rp[1], c1);
        c2 = fmaf(wi, rp[2], c2);
        tcur = tnext;
    }
    float* ob = out + (size_t)b * 16;
    ob[0] = c0 + bkgd[0] * (1.0f - acc);
    ob[1] = c1 + bkgd[1] * (1.0f - acc);
    ob[2] = c2 + bkgd[2] * (1.0f - acc);
    ob[3] = depth;
    ob[4] = acc;
    ob[5] = acc * o0x + wt0 * d0x;
    ob[6] = acc * o0y + wt0 * d0y;
    ob[7] = acc * o0z + wt0 * d0z;

    float ws = 0.f;
    for (int k = 1; k <= 62; k++) ws += w[k];
    const float pad = fmaxf(1e-5f - ws, 0.0f);
    const float add = pad * (1.0f / 62.0f);
    ws += pad;
    const float inv = 1.0f / ws;
    float cdf[64];
    cdf[0] = 0.0f;
    float cs = 0.f;
    for (int k = 1; k <= 61; k++) {
        cs += (w[k] + add) * inv;
        cdf[k] = fminf(cs, 1.0f);
    }
    cdf[62] = 1.0f;

    auto BIN = [&](int k) -> float { return 0.5f * (TV(k) + TV(k + 1)); };

    const float ueps = 1.1920929e-07f;
    const float du = (1.0f - ueps) * (1.0f / 127.0f);
    int idx = 0, ti = 0, p = 0;
    const size_t base = (size_t)b * NSF;
    for (int s = 0; s < NFI; s++) {
        const float u = (s == 127) ? (1.0f - ueps) : (float)s * du;
        while (idx < 61 && cdf[idx + 1] <= u) idx++;
        const float gg0 = cdf[idx], gg1 = cdf[idx + 1];
        float tt = (u - gg0) / (gg1 - gg0);
        if (!(tt == tt)) tt = 0.0f;
        tt = fminf(fmaxf(tt, 0.0f), 1.0f);
        const float bb0 = BIN(idx);
        const float z = fmaf(tt, BIN(idx + 1) - bb0, bb0);
        while (ti < NCO && TV(ti) <= z) { g_z[base + p] = TV(ti); p++; ti++; }
        g_z[base + p] = z; p++;
    }
    while (ti < NCO) { g_z[base + p] = TV(ti); p++; ti++; }
}

// ---------------- fine render: warp-per-ray (R11 validated) ----------------
__global__ void __launch_bounds__(256) fine_render_kernel(
    const float* __restrict__ org, const float* __restrict__ dirv,
    const float* __restrict__ bkgd, float* __restrict__ out)
{
    const int warp = threadIdx.x >> 5;
    const int lane = threadIdx.x & 31;
    const int b = blockIdx.x * 8 + warp;

    const float dxx = dirv[3*b+0], dyy = dirv[3*b+1], dzz = dirv[3*b+2];
    const float nrm = sqrtf(dxx*dxx + dyy*dyy + dzz*dzz);

    const float* zr = g_z + (size_t)b * NSF;
    const int i0 = 6 * lane;

    float z[7];
#pragma unroll
    for (int r = 0; r < 7; r++) {
        const int i = i0 + r;
        z[r] = (i < NSF) ? zr[i] : 0.0f;
    }
    float dd[6], pre[6];
    float tot = 0.f;   // scan excludes the last sample's ~1e10 dd (alpha-only term)
#pragma unroll
    for (int r = 0; r < 6; r++) {
        const int i = i0 + r;
        const float td = (i < NSF - 1) ? (z[r + 1] - z[r]) : 1e10f;
        dd[r] = g_sig_f[(size_t)b * NSF + i] * td * nrm;
        pre[r] = tot;
        if (i < NSF - 1) tot += dd[r];
    }
    const float excl = wscan_incl(tot) - tot;

    const float* rp = &g_rgb_f[((size_t)b * NSF + i0) * 3];
    float acc = 0.f, dep = 0.f, wz0 = 0.f, c0 = 0.f, c1 = 0.f, c2 = 0.f;
#pragma unroll
    for (int r = 0; r < 6; r++) {
        const float wi = (1.0f - __expf(-dd[r])) * __expf(-(excl + pre[r]));
        acc += wi;
        dep = fmaf(wi, z[r], dep);
        wz0 = fmaf(wi, g_z[i0 + r], wz0);     // samples_f[0] quirk: ray-0 z positions
        c0 = fmaf(wi, rp[3 * r + 0], c0);
        c1 = fmaf(wi, rp[3 * r + 1], c1);
        c2 = fmaf(wi, rp[3 * r + 2], c2);
    }
    acc = wred(acc); dep = wred(dep); wz0 = wred(wz0);
    c0 = wred(c0); c1 = wred(c1); c2 = wred(c2);
    if (lane == 0) {
        float* ob = out + (size_t)b * 16;
        ob[8]  = c0 + bkgd[0] * (1.0f - acc);
        ob[9]  = c1 + bkgd[1] * (1.0f - acc);
        ob[10] = c2 + bkgd[2] * (1.0f - acc);
        ob[11] = dep;
        ob[12] = acc;
        ob[13] = acc * org[0]  + wz0 * dirv[0];
        ob[14] = acc * org[1]  + wz0 * dirv[1];
        ob[15] = acc * org[2]  + wz0 * dirv[2];
    }
}

// ---------------- launch ----------------
extern "C" void kernel_launch(void* const* d_in, const int* in_sizes, int n_in,
                              void* d_out, int out_size)
{
    const float* org   = (const float*)d_in[0];
    const float* dirv  = (const float*)d_in[1];
    const float* nearp = (const float*)d_in[2];
    const float* farp  = (const float*)d_in[3];
    const float* bkgd  = (const float*)d_in[4];

    const float* w1c = (const float*)d_in[5];
    const float* b1c = (const float*)d_in[6];
    const float* w2c = (const float*)d_in[7];
    const float* b2c = (const float*)d_in[8];
    const float* wrc = (const float*)d_in[9];
    const float* brc = (const float*)d_in[10];
    const float* wdc = (const float*)d_in[11];
    const float* bdc = (const float*)d_in[12];

    const float* w1f = (const float*)d_in[13];
    const float* b1f = (const float*)d_in[14];
    const float* w2f = (const float*)d_in[15];
    const float* b2f = (const float*)d_in[16];
    const float* wrf = (const float*)d_in[17];
    const float* brf = (const float*)d_in[18];
    const float* wdf = (const float*)d_in[19];
    const float* bdf = (const float*)d_in[20];

    float* out = (float*)d_out;

    // coarse: 16384*64/16 = 65536 tiles; 4 warps * 8 tiles per block -> 2048 blocks
    mlp_mma_kernel<NCO, true, 8><<<2048, 128>>>(
        org, dirv, nearp, farp, w1c, b1c, w2c, b2c, wrc, brc, wdc, bdc);

    // scalar per-ray, 32-thread blocks to spread over all SMs
    coarse_post_kernel<<<BATCH / 32, 32>>>(org, dirv, nearp, farp, bkgd, out);

    // fine: 16384*192/16 = 196608 tiles -> 6144 blocks
    mlp_mma_kernel<NSF, false, 8><<<6144, 128>>>(
        org, dirv, nearp, farp, w1f, b1f, w2f, b2f, wrf, brf, wdf, bdf);

    // warp-per-ray: 8 rays per 256-thread block -> 2048 blocks
    fine_render_kernel<<<BATCH / 8, 256>>>(org, dirv, bkgd, out);
}